// round 1
// baseline (speedup 1.0000x reference)
#include <cuda_runtime.h>

#define NU 100000
#define NI 50000
#define NN 150000
#define HD 64
#define NE 1200000

// Scratch (static device globals — no dynamic allocation)
__device__ float g_bufA[NN * HD];
__device__ float g_bufB[NN * HD];
__device__ float g_h[NN * HD];
__device__ float g_dinv[NN];
__device__ int   g_cnt[NN];
__device__ float g_norm[NE];

// ---------------------------------------------------------------------------
// Setup: x0 = concat(users, items); cnt = 1 (self loop)
// ---------------------------------------------------------------------------
__global__ void k_init_x(const float* __restrict__ ue, const float* __restrict__ ie) {
    int t = blockIdx.x * blockDim.x + threadIdx.x;
    if (t < NN) g_cnt[t] = 1;
    if (t < NN * 16) {
        int row = t >> 4, c = t & 15;
        float4 v;
        if (row < NU) v = ((const float4*)ue)[row * 16 + c];
        else          v = ((const float4*)ie)[(row - NU) * 16 + c];
        ((float4*)g_bufA)[t] = v;
    }
}

__global__ void k_deg(const int* __restrict__ ei) {
    int e = blockIdx.x * blockDim.x + threadIdx.x;
    if (e < NE) atomicAdd(&g_cnt[ei[NE + e]], 1);
}

__global__ void k_dinv() {
    int i = blockIdx.x * blockDim.x + threadIdx.x;
    if (i < NN) g_dinv[i] = rsqrtf((float)g_cnt[i]);
}

__global__ void k_norm(const int* __restrict__ ei) {
    int e = blockIdx.x * blockDim.x + threadIdx.x;
    if (e < NE) g_norm[e] = g_dinv[ei[e]] * g_dinv[ei[NE + e]];
}

// ---------------------------------------------------------------------------
// GEMM: g_h = x @ W   (x: [NN,64], W: [64,64] row-major k,c)
// 256 threads/block, 32 rows/block, 8 threads per row x 8 cols each
// ---------------------------------------------------------------------------
__global__ void k_gemm(const float* __restrict__ x, const float* __restrict__ W) {
    __shared__ float Ws[64 * 64];
    __shared__ float Xs[32 * 68];   // padded stride 68 -> conflict-free scalar reads
    int tid  = threadIdx.x;
    int row0 = blockIdx.x * 32;

    #pragma unroll
    for (int i = 0; i < 4; i++)
        ((float4*)Ws)[tid + i * 256] = ((const float4*)W)[tid + i * 256];

    #pragma unroll
    for (int i = 0; i < 2; i++) {
        int idx = tid + i * 256;       // 0..511 = 32 rows x 16 float4
        int r = idx >> 4, c = idx & 15;
        int gr = row0 + r;
        float4 v = make_float4(0.f, 0.f, 0.f, 0.f);
        if (gr < NN) v = ((const float4*)x)[gr * 16 + c];
        *((float4*)&Xs[r * 68 + c * 4]) = v;
    }
    __syncthreads();

    int r  = tid >> 3;           // 0..31
    int cb = (tid & 7) << 3;     // 0,8,...,56
    float acc[8] = {0.f, 0.f, 0.f, 0.f, 0.f, 0.f, 0.f, 0.f};
    #pragma unroll
    for (int k = 0; k < 64; k++) {
        float xv = Xs[r * 68 + k];
        float4 w0 = *((float4*)&Ws[k * 64 + cb]);
        float4 w1 = *((float4*)&Ws[k * 64 + cb + 4]);
        acc[0] += xv * w0.x; acc[1] += xv * w0.y;
        acc[2] += xv * w0.z; acc[3] += xv * w0.w;
        acc[4] += xv * w1.x; acc[5] += xv * w1.y;
        acc[6] += xv * w1.z; acc[7] += xv * w1.w;
    }
    int gr = row0 + r;
    if (gr < NN) {
        float4* o = (float4*)&g_h[gr * 64 + cb];
        o[0] = make_float4(acc[0], acc[1], acc[2], acc[3]);
        o[1] = make_float4(acc[4], acc[5], acc[6], acc[7]);
    }
}

// ---------------------------------------------------------------------------
// Init aggregation target: xn = b + dinv^2 * h   (self-loop term, race-free)
// final=1 remaps node row -> d_out row (items shifted by NU)
// ---------------------------------------------------------------------------
__global__ void k_initxn(const float* __restrict__ b, float* __restrict__ xn, int fin) {
    int t = blockIdx.x * blockDim.x + threadIdx.x;
    if (t >= NN * 16) return;
    int row = t >> 4, c = t & 15;
    float dd = g_dinv[row];
    float s  = dd * dd;
    float4 hv = ((const float4*)g_h)[row * 16 + c];
    float4 bv = ((const float4*)b)[c];
    float4 o;
    o.x = bv.x + s * hv.x;
    o.y = bv.y + s * hv.y;
    o.z = bv.z + s * hv.z;
    o.w = bv.w + s * hv.w;
    int orow = fin ? (row < NU ? row : row + NU) : row;
    ((float4*)xn)[orow * 16 + c] = o;
}

// ---------------------------------------------------------------------------
// Edge scatter: xn[dst] += norm * h[src]   via red.global.add.v4.f32
// 16 threads per edge, each handles one float4 (4 of 64 cols)
// ---------------------------------------------------------------------------
__global__ void k_scatter(const int* __restrict__ ei, float* __restrict__ xn, int fin) {
    int t = blockIdx.x * blockDim.x + threadIdx.x;
    if (t >= NE * 16) return;
    int e = t >> 4, c = (t & 15) << 2;
    int s = ei[e];
    int d = ei[NE + e];
    float nrm = g_norm[e];
    float4 hv = *((const float4*)&g_h[s * 64 + c]);
    if (fin) d = (d < NU) ? d : d + NU;
    float* p = &xn[d * 64 + c];
    asm volatile("red.global.add.v4.f32 [%0], {%1, %2, %3, %4};"
                 :: "l"(p), "f"(hv.x * nrm), "f"(hv.y * nrm),
                    "f"(hv.z * nrm), "f"(hv.w * nrm)
                 : "memory");
}

// ---------------------------------------------------------------------------
// Copy raw embeddings into output segments 1 (users) and 3 (items)
// ---------------------------------------------------------------------------
__global__ void k_embcopy(const float* __restrict__ ue, const float* __restrict__ ie,
                          float* __restrict__ out) {
    int t = blockIdx.x * blockDim.x + threadIdx.x;
    if (t < NU * 16) {
        ((float4*)out)[NU * 16 + t] = ((const float4*)ue)[t];
    } else if (t < NN * 16) {
        int q = t - NU * 16;
        ((float4*)out)[(2 * NU + NI) * 16 + q] = ((const float4*)ie)[q];
    }
}

// ---------------------------------------------------------------------------
extern "C" void kernel_launch(void* const* d_in, const int* in_sizes, int n_in,
                              void* d_out, int out_size) {
    const int*   ei = (const int*)d_in[0];
    const float* ue = (const float*)d_in[1];
    const float* ie = (const float*)d_in[2];
    const float* Ws = (const float*)d_in[3];
    const float* bs = (const float*)d_in[4];
    float* out = (float*)d_out;

    float* xbufs[2];
    cudaGetSymbolAddress((void**)&xbufs[0], g_bufA);
    cudaGetSymbolAddress((void**)&xbufs[1], g_bufB);

    const int TB = 256;
    k_init_x <<<(NN * 16 + TB - 1) / TB, TB>>>(ue, ie);
    k_deg    <<<(NE + TB - 1) / TB, TB>>>(ei);
    k_dinv   <<<(NN + TB - 1) / TB, TB>>>();
    k_norm   <<<(NE + TB - 1) / TB, TB>>>(ei);
    k_embcopy<<<(NN * 16 + TB - 1) / TB, TB>>>(ue, ie, out);

    const float* xin = xbufs[0];
    for (int l = 0; l < 3; l++) {
        float* xout = (l == 2) ? out : xbufs[(l + 1) & 1];
        int fin = (l == 2) ? 1 : 0;
        k_gemm   <<<(NN + 31) / 32, TB>>>(xin, Ws + l * 64 * 64);
        k_initxn <<<(NN * 16 + TB - 1) / TB, TB>>>(bs + l * 64, xout, fin);
        k_scatter<<<(NE * 16 + TB - 1) / TB, TB>>>(ei, xout, fin);
        xin = xout;
    }
}

// round 2
// speedup vs baseline: 1.1745x; 1.1745x over previous
#include <cuda_runtime.h>

#define NU 100000
#define NI 50000
#define NN 150000
#define HD 64
#define NE 1200000
#define SCAN_B 1024
#define NBLK ((NN + SCAN_B - 1) / SCAN_B)   // 147

// Scratch (static device globals)
__device__ float g_x[NN * HD];       // ping buffer for intermediate layers
__device__ float g_h[NN * HD];       // h = x @ W
__device__ int   g_cnt[NN];          // in-degree incl self loop
__device__ int   g_tmp[NN];          // block-local inclusive scan
__device__ int   g_bsum[NBLK];       // per-block sums
__device__ int   g_off[NN + 1];      // CSR offsets (by dst)
__device__ int   g_cur[NN];          // fill cursors
__device__ int2  g_edge[NE];         // {src, norm bits}, sorted by dst

#define FMA2(acc, a, b) \
    asm("fma.rn.f32x2 %0, %1, %2, %0;" : "+l"(acc) : "l"(a), "l"(b))

// ---------------------------------------------------------------------------
__global__ void k_cntinit() {
    int i = blockIdx.x * blockDim.x + threadIdx.x;
    if (i < NN) g_cnt[i] = 1;
}

__global__ void k_deg(const int* __restrict__ ei) {
    int e = blockIdx.x * blockDim.x + threadIdx.x;
    if (e < NE) atomicAdd(&g_cnt[ei[NE + e]], 1);
}

// ---------------------------------------------------------------------------
// Exclusive scan of edge in-degree (cnt-1) -> g_off, g_cur
// ---------------------------------------------------------------------------
__global__ void k_scan1() {
    __shared__ int ws[32];
    int i = blockIdx.x * SCAN_B + threadIdx.x;
    int lane = threadIdx.x & 31, wid = threadIdx.x >> 5;
    int x = (i < NN) ? (g_cnt[i] - 1) : 0;
    #pragma unroll
    for (int o = 1; o < 32; o <<= 1) {
        int y = __shfl_up_sync(0xffffffffu, x, o);
        if (lane >= o) x += y;
    }
    if (lane == 31) ws[wid] = x;
    __syncthreads();
    if (wid == 0) {
        int s = ws[lane];
        #pragma unroll
        for (int o = 1; o < 32; o <<= 1) {
            int y = __shfl_up_sync(0xffffffffu, s, o);
            if (lane >= o) s += y;
        }
        ws[lane] = s;
    }
    __syncthreads();
    int incl = x + (wid > 0 ? ws[wid - 1] : 0);
    if (i < NN) g_tmp[i] = incl;
    if (threadIdx.x == SCAN_B - 1) g_bsum[blockIdx.x] = incl;
}

__global__ void k_scan2() {
    if (threadIdx.x == 0) {
        int a = 0;
        for (int b = 0; b < NBLK; b++) { a += g_bsum[b]; g_bsum[b] = a; }
    }
}

__global__ void k_scan3() {
    int i = blockIdx.x * SCAN_B + threadIdx.x;
    if (i >= NN) return;
    int incl = g_tmp[i] + (blockIdx.x > 0 ? g_bsum[blockIdx.x - 1] : 0);
    g_off[i + 1] = incl;
    g_cur[i] = incl - (g_cnt[i] - 1);
    if (i == 0) g_off[0] = 0;
}

// ---------------------------------------------------------------------------
// Bucket fill: edges sorted by dst, with precomputed norm
// ---------------------------------------------------------------------------
__global__ void k_fill(const int* __restrict__ ei) {
    int e = blockIdx.x * blockDim.x + threadIdx.x;
    if (e >= NE) return;
    int s = ei[e];
    int d = ei[NE + e];
    float nrm = rsqrtf((float)g_cnt[s]) * rsqrtf((float)g_cnt[d]);
    int pos = atomicAdd(&g_cur[d], 1);
    g_edge[pos] = make_int2(s, __float_as_int(nrm));
}

// ---------------------------------------------------------------------------
// GEMM: g_h = x @ W, packed f32x2 FMA. Layer 0 reads ue/ie directly.
// 256 thr/block: 32 rows x (8 thr x 8 cols)
// ---------------------------------------------------------------------------
__global__ void k_gemm(const float* __restrict__ xA, const float* __restrict__ xB,
                       const float* __restrict__ W, int split) {
    __shared__ float Ws[64 * 64];
    __shared__ float Xs[32 * 68];
    int tid  = threadIdx.x;
    int row0 = blockIdx.x * 32;

    #pragma unroll
    for (int i = 0; i < 4; i++)
        ((float4*)Ws)[tid + i * 256] = ((const float4*)W)[tid + i * 256];

    #pragma unroll
    for (int i = 0; i < 2; i++) {
        int idx = tid + i * 256;
        int r = idx >> 4, c = idx & 15;
        int gr = row0 + r;
        float4 v = make_float4(0.f, 0.f, 0.f, 0.f);
        if (gr < NN) {
            const float4* src = (gr < split) ? (const float4*)&xA[(size_t)gr * 64]
                                             : (const float4*)&xB[(size_t)(gr - split) * 64];
            v = src[c];
        }
        *((float4*)&Xs[r * 68 + c * 4]) = v;
    }
    __syncthreads();

    int r  = tid >> 3;
    int cb = (tid & 7) << 3;
    unsigned long long acc0 = 0, acc1 = 0, acc2 = 0, acc3 = 0;
    #pragma unroll
    for (int k = 0; k < 64; k++) {
        float xv = Xs[r * 68 + k];
        unsigned int xi = __float_as_uint(xv);
        unsigned long long xvv;
        asm("mov.b64 %0, {%1, %1};" : "=l"(xvv) : "r"(xi));
        const ulonglong2* wp = (const ulonglong2*)&Ws[k * 64 + cb];
        ulonglong2 wa = wp[0], wb = wp[1];
        FMA2(acc0, xvv, wa.x);
        FMA2(acc1, xvv, wa.y);
        FMA2(acc2, xvv, wb.x);
        FMA2(acc3, xvv, wb.y);
    }
    int gr = row0 + r;
    if (gr < NN) {
        unsigned int a, b2, c2, d2, e2, f2, g2, h2;
        asm("mov.b64 {%0, %1}, %2;" : "=r"(a),  "=r"(b2) : "l"(acc0));
        asm("mov.b64 {%0, %1}, %2;" : "=r"(c2), "=r"(d2) : "l"(acc1));
        asm("mov.b64 {%0, %1}, %2;" : "=r"(e2), "=r"(f2) : "l"(acc2));
        asm("mov.b64 {%0, %1}, %2;" : "=r"(g2), "=r"(h2) : "l"(acc3));
        float4* o = (float4*)&g_h[(size_t)gr * 64 + cb];
        o[0] = make_float4(__uint_as_float(a),  __uint_as_float(b2),
                           __uint_as_float(c2), __uint_as_float(d2));
        o[1] = make_float4(__uint_as_float(e2), __uint_as_float(f2),
                           __uint_as_float(g2), __uint_as_float(h2));
    }
}

// ---------------------------------------------------------------------------
// Gather: x[dst] = b + h[dst]/deg + sum_{e in CSR[dst]} nrm_e * h[src_e]
// 16 threads per node, each owns one float4 column chunk.
// ---------------------------------------------------------------------------
__global__ void k_gather(const float* __restrict__ b, float* __restrict__ xout, int fin) {
    int t = blockIdx.x * blockDim.x + threadIdx.x;
    int node = t >> 4;
    int c = t & 15;
    if (node >= NN) return;

    int beg = g_off[node];
    int end = g_off[node + 1];
    float inv = 1.0f / (float)g_cnt[node];
    float4 hv = ((const float4*)g_h)[node * 16 + c];
    float4 bv = ((const float4*)b)[c];
    float4 acc;
    acc.x = bv.x + inv * hv.x;
    acc.y = bv.y + inv * hv.y;
    acc.z = bv.z + inv * hv.z;
    acc.w = bv.w + inv * hv.w;

    for (int j = beg; j < end; j++) {
        int2 ed = __ldg(&g_edge[j]);
        float w = __int_as_float(ed.y);
        float4 h = ((const float4*)g_h)[(size_t)ed.x * 16 + c];
        acc.x += w * h.x;
        acc.y += w * h.y;
        acc.z += w * h.z;
        acc.w += w * h.w;
    }

    int orow = fin ? (node < NU ? node : node + NU) : node;
    ((float4*)xout)[orow * 16 + c] = acc;
}

// ---------------------------------------------------------------------------
__global__ void k_embcopy(const float* __restrict__ ue, const float* __restrict__ ie,
                          float* __restrict__ out) {
    int t = blockIdx.x * blockDim.x + threadIdx.x;
    if (t < NU * 16) {
        ((float4*)out)[NU * 16 + t] = ((const float4*)ue)[t];
    } else if (t < NN * 16) {
        int q = t - NU * 16;
        ((float4*)out)[(2 * NU + NI) * 16 + q] = ((const float4*)ie)[q];
    }
}

// ---------------------------------------------------------------------------
extern "C" void kernel_launch(void* const* d_in, const int* in_sizes, int n_in,
                              void* d_out, int out_size) {
    const int*   ei = (const int*)d_in[0];
    const float* ue = (const float*)d_in[1];
    const float* ie = (const float*)d_in[2];
    const float* Ws = (const float*)d_in[3];
    const float* bs = (const float*)d_in[4];
    float* out = (float*)d_out;

    float* xbuf;
    cudaGetSymbolAddress((void**)&xbuf, g_x);

    const int TB = 256;
    k_cntinit<<<(NN + TB - 1) / TB, TB>>>();
    k_deg    <<<(NE + TB - 1) / TB, TB>>>(ei);
    k_scan1  <<<NBLK, SCAN_B>>>();
    k_scan2  <<<1, 32>>>();
    k_scan3  <<<NBLK, SCAN_B>>>();
    k_fill   <<<(NE + TB - 1) / TB, TB>>>(ei);
    k_embcopy<<<(NN * 16 + TB - 1) / TB, TB>>>(ue, ie, out);

    for (int l = 0; l < 3; l++) {
        int fin = (l == 2) ? 1 : 0;
        float* xout = fin ? out : xbuf;
        if (l == 0)
            k_gemm<<<(NN + 31) / 32, TB>>>(ue, ie, Ws, NU);
        else
            k_gemm<<<(NN + 31) / 32, TB>>>(xbuf, xbuf, Ws + l * 64 * 64, NN);
        k_gather<<<(NN * 16 + TB - 1) / TB, TB>>>(bs + l * 64, xout, fin);
    }
}

// round 3
// speedup vs baseline: 1.8350x; 1.5624x over previous
#include <cuda_runtime.h>

#define NU 100000
#define NI 50000
#define NN 150000
#define HD 64
#define NE 1200000
#define SCAN_B 1024
#define NBLK ((NN + SCAN_B - 1) / SCAN_B)   // 147

// Scratch (static device globals)
__device__ float g_bufA[NN * HD];
__device__ float g_bufB[NN * HD];
__device__ float g_u1[NN];
__device__ float g_u2[NN];
__device__ int   g_cnt[NN];          // edge in-degree (self loop NOT included)
__device__ int   g_tmp[NN];
__device__ int   g_bsum[NBLK];
__device__ int   g_off[NN + 1];
__device__ int   g_cur[NN];
__device__ int2  g_edge[NE];         // {src, norm bits}, bucketed by dst
__device__ float g_W123[HD * HD];    // W1@W2@W3
__device__ float g_bv1[HD];          // b2@W3
__device__ float g_bv2[HD];          // b1@W2@W3

// ---------------------------------------------------------------------------
__global__ void k_deg(const int* __restrict__ ei) {
    int e = blockIdx.x * blockDim.x + threadIdx.x;
    if (e < NE) atomicAdd(&g_cnt[ei[NE + e]], 1);
}

// ---------------------------------------------------------------------------
// Scan of g_cnt -> CSR offsets
// ---------------------------------------------------------------------------
__global__ void k_scan1() {
    __shared__ int ws[32];
    int i = blockIdx.x * SCAN_B + threadIdx.x;
    int lane = threadIdx.x & 31, wid = threadIdx.x >> 5;
    int x = (i < NN) ? g_cnt[i] : 0;
    #pragma unroll
    for (int o = 1; o < 32; o <<= 1) {
        int y = __shfl_up_sync(0xffffffffu, x, o);
        if (lane >= o) x += y;
    }
    if (lane == 31) ws[wid] = x;
    __syncthreads();
    if (wid == 0) {
        int s = ws[lane];
        #pragma unroll
        for (int o = 1; o < 32; o <<= 1) {
            int y = __shfl_up_sync(0xffffffffu, s, o);
            if (lane >= o) s += y;
        }
        ws[lane] = s;
    }
    __syncthreads();
    int incl = x + (wid > 0 ? ws[wid - 1] : 0);
    if (i < NN) g_tmp[i] = incl;
    if (threadIdx.x == SCAN_B - 1) g_bsum[blockIdx.x] = incl;
}

__global__ void k_scan2() {   // 256 threads, parallel scan of 147 block sums
    __shared__ int ws[8];
    int t = threadIdx.x;
    int lane = t & 31, wid = t >> 5;
    int x = (t < NBLK) ? g_bsum[t] : 0;
    #pragma unroll
    for (int o = 1; o < 32; o <<= 1) {
        int y = __shfl_up_sync(0xffffffffu, x, o);
        if (lane >= o) x += y;
    }
    if (lane == 31) ws[wid] = x;
    __syncthreads();
    if (wid == 0 && lane < 8) {
        int s = ws[lane];
        #pragma unroll
        for (int o = 1; o < 8; o <<= 1) {
            int y = __shfl_up_sync(0xffu, s, o);
            if (lane >= o) s += y;
        }
        ws[lane] = s;
    }
    __syncthreads();
    int incl = x + (wid > 0 ? ws[wid - 1] : 0);
    if (t < NBLK) g_bsum[t] = incl;
}

__global__ void k_scan3() {
    int i = blockIdx.x * SCAN_B + threadIdx.x;
    if (i >= NN) return;
    int incl = g_tmp[i] + (blockIdx.x > 0 ? g_bsum[blockIdx.x - 1] : 0);
    g_off[i + 1] = incl;
    g_cur[i] = incl - g_cnt[i];
    if (i == 0) g_off[0] = 0;
}

// ---------------------------------------------------------------------------
__global__ void k_fill(const int* __restrict__ ei) {
    int e = blockIdx.x * blockDim.x + threadIdx.x;
    if (e >= NE) return;
    int s = ei[e];
    int d = ei[NE + e];
    float nrm = rsqrtf((float)(g_cnt[s] + 1)) * rsqrtf((float)(g_cnt[d] + 1));
    int pos = atomicAdd(&g_cur[d], 1);
    g_edge[pos] = make_int2(s, __float_as_int(nrm));
}

// ---------------------------------------------------------------------------
// W123 = W1@W2@W3, bv2 = b1@W2@W3, bv1 = b2@W3. One block, 256 threads.
// ---------------------------------------------------------------------------
__global__ void k_wprod(const float* __restrict__ Ws, const float* __restrict__ bs) {
    __shared__ float A[4096], B[4096], T[4096];
    int tid = threadIdx.x;
    #pragma unroll
    for (int i = 0; i < 4; i++) {
        ((float4*)A)[tid + i * 256] = ((const float4*)(Ws + 4096))[tid + i * 256]; // W2
        ((float4*)B)[tid + i * 256] = ((const float4*)(Ws + 8192))[tid + i * 256]; // W3
    }
    __syncthreads();
    #pragma unroll
    for (int i = 0; i < 16; i++) {             // T = W2@W3
        int idx = tid * 16 + i, r = idx >> 6, c = idx & 63;
        float s = 0.f;
        #pragma unroll
        for (int k = 0; k < 64; k++) s += A[r * 64 + k] * B[k * 64 + c];
        T[idx] = s;
    }
    __syncthreads();
    #pragma unroll
    for (int i = 0; i < 4; i++)
        ((float4*)A)[tid + i * 256] = ((const float4*)Ws)[tid + i * 256];          // W1
    __syncthreads();
    #pragma unroll
    for (int i = 0; i < 16; i++) {             // W123 = W1@T
        int idx = tid * 16 + i, r = idx >> 6, c = idx & 63;
        float s = 0.f;
        #pragma unroll
        for (int k = 0; k < 64; k++) s += A[r * 64 + k] * T[k * 64 + c];
        g_W123[idx] = s;
    }
    if (tid < 64) {                            // bv2 = b1@T
        float s = 0.f;
        #pragma unroll
        for (int k = 0; k < 64; k++) s += bs[k] * T[k * 64 + tid];
        g_bv2[tid] = s;
    } else if (tid < 128) {                    // bv1 = b2@W3
        int c = tid - 64;
        float s = 0.f;
        #pragma unroll
        for (int k = 0; k < 64; k++) s += bs[64 + k] * B[k * 64 + c];
        g_bv1[c] = s;
    }
}

// ---------------------------------------------------------------------------
// Aggregation: y[i] = dinv_i^2 * x[i] + sum_e nrm_e * x[src_e]
// 16 threads/node; cooperative coalesced edge loads + width-16 shuffles.
// Optionally also computes u_out = A~ @ u_in (lane 0 of each group).
// ---------------------------------------------------------------------------
__global__ void k_agg(const float* __restrict__ xA, const float* __restrict__ xB,
                      int split,
                      const float* __restrict__ u_in, float* __restrict__ u_out,
                      float* __restrict__ yout) {
    int t = blockIdx.x * blockDim.x + threadIdx.x;
    int node = t >> 4;
    int c = t & 15;
    unsigned gmask = 0xFFFFu << (threadIdx.x & 16);

    int beg = g_off[node];
    int end = g_off[node + 1];
    float inv = 1.0f / (float)(end - beg + 1);

    const float4* sp = (node < split) ? (const float4*)&xA[(size_t)node * 64]
                                      : (const float4*)&xB[(size_t)(node - split) * 64];
    float4 acc = sp[c];
    acc.x *= inv; acc.y *= inv; acc.z *= inv; acc.w *= inv;
    float uacc = inv * (u_in ? u_in[node] : 1.0f);

    for (int j0 = beg; j0 < end; j0 += 16) {
        int idx = j0 + c;
        int2 ed = make_int2(0, 0);
        if (idx < end) ed = g_edge[idx];
        int m = min(16, end - j0);
        #pragma unroll 4
        for (int k = 0; k < m; k++) {
            int   s = __shfl_sync(gmask, ed.x, k, 16);
            float w = __int_as_float(__shfl_sync(gmask, ed.y, k, 16));
            const float4* hp = (s < split) ? (const float4*)&xA[(size_t)s * 64]
                                           : (const float4*)&xB[(size_t)(s - split) * 64];
            float4 h = hp[c];
            acc.x += w * h.x; acc.y += w * h.y;
            acc.z += w * h.z; acc.w += w * h.w;
            if (u_out && c == 0)
                uacc += w * (u_in ? u_in[s] : 1.0f);
        }
    }
    ((float4*)yout)[node * 16 + c] = acc;
    if (u_out && c == 0) u_out[node] = uacc;
}

// ---------------------------------------------------------------------------
// Final GEMM: out[remap(n)] = y3[n] @ W123 + u2[n]*bv2 + u1[n]*bv1 + b3
// ---------------------------------------------------------------------------
__global__ void k_gemm_final(const float* __restrict__ x, const float* __restrict__ b3,
                             float* __restrict__ out) {
    __shared__ float Ws[64 * 64];
    __shared__ float Xs[32 * 68];
    int tid  = threadIdx.x;
    int row0 = blockIdx.x * 32;

    #pragma unroll
    for (int i = 0; i < 4; i++)
        ((float4*)Ws)[tid + i * 256] = ((const float4*)g_W123)[tid + i * 256];

    #pragma unroll
    for (int i = 0; i < 2; i++) {
        int idx = tid + i * 256;
        int r = idx >> 4, cc = idx & 15;
        int gr = row0 + r;
        float4 v = make_float4(0.f, 0.f, 0.f, 0.f);
        if (gr < NN) v = ((const float4*)x)[(size_t)gr * 16 + cc];
        *((float4*)&Xs[r * 68 + cc * 4]) = v;
    }
    __syncthreads();

    int r  = tid >> 3;
    int cb = (tid & 7) << 3;
    int gr = row0 + r;
    float acc[8];
    {
        float un1 = (gr < NN) ? g_u1[gr] : 0.f;
        float un2 = (gr < NN) ? g_u2[gr] : 0.f;
        #pragma unroll
        for (int i = 0; i < 8; i++)
            acc[i] = b3[cb + i] + un2 * g_bv2[cb + i] + un1 * g_bv1[cb + i];
    }
    #pragma unroll
    for (int k = 0; k < 64; k++) {
        float xv = Xs[r * 68 + k];
        float4 w0 = *((float4*)&Ws[k * 64 + cb]);
        float4 w1 = *((float4*)&Ws[k * 64 + cb + 4]);
        acc[0] += xv * w0.x; acc[1] += xv * w0.y;
        acc[2] += xv * w0.z; acc[3] += xv * w0.w;
        acc[4] += xv * w1.x; acc[5] += xv * w1.y;
        acc[6] += xv * w1.z; acc[7] += xv * w1.w;
    }
    if (gr < NN) {
        int orow = (gr < NU) ? gr : gr + NU;
        float4* o = (float4*)&out[(size_t)orow * 64 + cb];
        o[0] = make_float4(acc[0], acc[1], acc[2], acc[3]);
        o[1] = make_float4(acc[4], acc[5], acc[6], acc[7]);
    }
}

// ---------------------------------------------------------------------------
__global__ void k_embcopy(const float* __restrict__ ue, const float* __restrict__ ie,
                          float* __restrict__ out) {
    int t = blockIdx.x * blockDim.x + threadIdx.x;
    if (t < NU * 16) {
        ((float4*)out)[NU * 16 + t] = ((const float4*)ue)[t];
    } else if (t < NN * 16) {
        int q = t - NU * 16;
        ((float4*)out)[(2 * NU + NI) * 16 + q] = ((const float4*)ie)[q];
    }
}

// ---------------------------------------------------------------------------
extern "C" void kernel_launch(void* const* d_in, const int* in_sizes, int n_in,
                              void* d_out, int out_size) {
    const int*   ei = (const int*)d_in[0];
    const float* ue = (const float*)d_in[1];
    const float* ie = (const float*)d_in[2];
    const float* Ws = (const float*)d_in[3];
    const float* bs = (const float*)d_in[4];
    float* out = (float*)d_out;

    float *bufA, *bufB, *u1, *u2, *cntp;
    cudaGetSymbolAddress((void**)&bufA, g_bufA);
    cudaGetSymbolAddress((void**)&bufB, g_bufB);
    cudaGetSymbolAddress((void**)&u1,   g_u1);
    cudaGetSymbolAddress((void**)&u2,   g_u2);
    cudaGetSymbolAddress((void**)&cntp, g_cnt);

    const int TB = 256;
    cudaMemsetAsync(cntp, 0, NN * sizeof(int));
    k_deg   <<<(NE + TB - 1) / TB, TB>>>(ei);
    k_scan1 <<<NBLK, SCAN_B>>>();
    k_scan2 <<<1, 256>>>();
    k_scan3 <<<NBLK, SCAN_B>>>();
    k_fill  <<<(NE + TB - 1) / TB, TB>>>(ei);
    k_wprod <<<1, 256>>>(Ws, bs);

    // y1 = A~ X0 (+u1),  y2 = A~ y1 (+u2),  y3 = A~ y2
    k_agg<<<NN * 16 / TB, TB>>>(ue,   ie,   NU, nullptr, u1,      bufA);
    k_agg<<<NN * 16 / TB, TB>>>(bufA, bufA, NN, u1,      u2,      bufB);
    k_agg<<<NN * 16 / TB, TB>>>(bufB, bufB, NN, nullptr, nullptr, bufA);

    k_gemm_final<<<(NN + 31) / 32, TB>>>(bufA, bs + 2 * 64, out);
    k_embcopy   <<<(NN * 16 + TB - 1) / TB, TB>>>(ue, ie, out);
}

// round 4
// speedup vs baseline: 1.9681x; 1.0725x over previous
#include <cuda_runtime.h>

#define NU 100000
#define NI 50000
#define NN 150000
#define HD 64
#define NE 1200000
#define SCAN_B 1024
#define NBLK ((NN + SCAN_B - 1) / SCAN_B)   // 147

typedef unsigned long long ull;

// Scratch (static device globals)
__device__ float g_bufA[NN * HD];
__device__ float g_bufB[NN * HD];
__device__ float g_bufC[NN * HD];    // X0 = concat(users, items)
__device__ float g_u1[NN];
__device__ float g_u2[NN];
__device__ int   g_cnt[NN];          // edge in-degree (self loop NOT included)
__device__ int   g_tmp[NN];
__device__ int   g_bsum[NBLK];
__device__ int   g_off[NN + 1];
__device__ int   g_cur[NN];
__device__ int2  g_edge[NE];         // {src, norm bits}, bucketed by dst
__device__ float g_W123[HD * HD];    // W1@W2@W3
__device__ float g_bv1[HD];          // b2@W3
__device__ float g_bv2[HD];          // b1@W2@W3

#define FMA2(acc, a, b) \
    asm("fma.rn.f32x2 %0, %1, %2, %0;" : "+l"(acc) : "l"(a), "l"(b))
#define MUL2(d, a, b) \
    asm("mul.rn.f32x2 %0, %1, %2;" : "=l"(d) : "l"(a), "l"(b))

// ---------------------------------------------------------------------------
// Prep: bufC = concat(ue, ie); out emb segments (1 and 3)
// ---------------------------------------------------------------------------
__global__ void k_prep(const float* __restrict__ ue, const float* __restrict__ ie,
                       float* __restrict__ out) {
    int t = blockIdx.x * blockDim.x + threadIdx.x;
    if (t < NU * 16) {
        float4 v = ((const float4*)ue)[t];
        ((float4*)g_bufC)[t] = v;
        ((float4*)out)[NU * 16 + t] = v;
    } else if (t < NN * 16) {
        int q = t - NU * 16;
        float4 v = ((const float4*)ie)[q];
        ((float4*)g_bufC)[t] = v;
        ((float4*)out)[(2 * NU + NI) * 16 + q] = v;
    }
}

// ---------------------------------------------------------------------------
__global__ void k_deg(const int* __restrict__ ei) {
    int e = blockIdx.x * blockDim.x + threadIdx.x;
    if (e < NE) atomicAdd(&g_cnt[ei[NE + e]], 1);
}

// ---------------------------------------------------------------------------
// Scan step 1: per-block inclusive scan of g_cnt
// ---------------------------------------------------------------------------
__global__ void k_scan1() {
    __shared__ int ws[32];
    int i = blockIdx.x * SCAN_B + threadIdx.x;
    int lane = threadIdx.x & 31, wid = threadIdx.x >> 5;
    int x = (i < NN) ? g_cnt[i] : 0;
    #pragma unroll
    for (int o = 1; o < 32; o <<= 1) {
        int y = __shfl_up_sync(0xffffffffu, x, o);
        if (lane >= o) x += y;
    }
    if (lane == 31) ws[wid] = x;
    __syncthreads();
    if (wid == 0) {
        int s = ws[lane];
        #pragma unroll
        for (int o = 1; o < 32; o <<= 1) {
            int y = __shfl_up_sync(0xffffffffu, s, o);
            if (lane >= o) s += y;
        }
        ws[lane] = s;
    }
    __syncthreads();
    int incl = x + (wid > 0 ? ws[wid - 1] : 0);
    if (i < NN) g_tmp[i] = incl;
    if (threadIdx.x == SCAN_B - 1) g_bsum[blockIdx.x] = incl;
}

// ---------------------------------------------------------------------------
// Scan step 2 (merged): each block computes its own base = sum(bsum[0..bid-1])
// via smem atomic reduction, then finalizes offsets + cursors.
// ---------------------------------------------------------------------------
__global__ void k_scanfin() {
    __shared__ int base;
    if (threadIdx.x == 0) base = 0;
    __syncthreads();
    if (threadIdx.x < blockIdx.x) atomicAdd(&base, g_bsum[threadIdx.x]);
    __syncthreads();
    int i = blockIdx.x * SCAN_B + threadIdx.x;
    if (i >= NN) return;
    int incl = g_tmp[i] + base;
    g_off[i + 1] = incl;
    g_cur[i] = incl - g_cnt[i];
    if (i == 0) g_off[0] = 0;
}

// ---------------------------------------------------------------------------
__global__ void k_fill(const int* __restrict__ ei) {
    int e = blockIdx.x * blockDim.x + threadIdx.x;
    if (e >= NE) return;
    int s = ei[e];
    int d = ei[NE + e];
    float nrm = rsqrtf((float)(g_cnt[s] + 1)) * rsqrtf((float)(g_cnt[d] + 1));
    int pos = atomicAdd(&g_cur[d], 1);
    g_edge[pos] = make_int2(s, __float_as_int(nrm));
}

// ---------------------------------------------------------------------------
// Aggregation: y[i] = inv_i * x[i] + sum_e nrm_e * x[src_e]
// 8 threads/node, each owns 8 cols (2x LDG.128). Width-8 shuffle broadcast.
// ---------------------------------------------------------------------------
template<bool UIN, bool UOUT>
__global__ void k_agg(const float* __restrict__ x,
                      const float* __restrict__ u_in, float* __restrict__ u_out,
                      float* __restrict__ y) {
    int t = blockIdx.x * blockDim.x + threadIdx.x;
    int node = t >> 3;
    int c = t & 7;
    if (node >= NN) return;
    unsigned gmask = 0xFFu << (threadIdx.x & 24);

    int beg = g_off[node];
    int end = g_off[node + 1];
    float inv = 1.0f / (float)(end - beg + 1);
    ull pinv;
    asm("mov.b64 %0, {%1, %1};" : "=l"(pinv) : "f"(inv));

    const float* xc = x + c * 8;
    ulonglong2 s0 = *(const ulonglong2*)(xc + (size_t)node * 64);
    ulonglong2 s1 = *(const ulonglong2*)(xc + (size_t)node * 64 + 4);
    ull acc0, acc1, acc2, acc3;
    MUL2(acc0, s0.x, pinv); MUL2(acc1, s0.y, pinv);
    MUL2(acc2, s1.x, pinv); MUL2(acc3, s1.y, pinv);

    float uacc = UOUT ? inv * (UIN ? u_in[node] : 1.0f) : 0.0f;

    for (int j0 = beg; j0 < end; j0 += 8) {
        int idx = j0 + c;
        int2 ed = make_int2(0, 0);
        if (idx < end) ed = g_edge[idx];
        int m = min(8, end - j0);
        #pragma unroll 4
        for (int k = 0; k < m; k++) {
            int      s  = __shfl_sync(gmask, ed.x, k, 8);
            unsigned wb = (unsigned)__shfl_sync(gmask, ed.y, k, 8);
            ull ww;
            asm("mov.b64 %0, {%1, %1};" : "=l"(ww) : "r"(wb));
            ulonglong2 h0 = *(const ulonglong2*)(xc + (size_t)s * 64);
            ulonglong2 h1 = *(const ulonglong2*)(xc + (size_t)s * 64 + 4);
            FMA2(acc0, ww, h0.x); FMA2(acc1, ww, h0.y);
            FMA2(acc2, ww, h1.x); FMA2(acc3, ww, h1.y);
            if (UOUT && c == 0)
                uacc += __uint_as_float(wb) * (UIN ? u_in[s] : 1.0f);
        }
    }

    ulonglong2* yo = (ulonglong2*)(y + (size_t)node * 64 + c * 8);
    yo[0] = make_ulonglong2(acc0, acc1);
    yo[1] = make_ulonglong2(acc2, acc3);
    if (UOUT && c == 0) u_out[node] = uacc;
}

// ---------------------------------------------------------------------------
// W123 = W1@W2@W3, bv2 = b1@W2@W3, bv1 = b2@W3. One block, 256 threads.
// ---------------------------------------------------------------------------
__global__ void k_wprod(const float* __restrict__ Ws, const float* __restrict__ bs) {
    __shared__ float A[4096], B[4096], T[4096];
    int tid = threadIdx.x;
    #pragma unroll
    for (int i = 0; i < 4; i++) {
        ((float4*)A)[tid + i * 256] = ((const float4*)(Ws + 4096))[tid + i * 256]; // W2
        ((float4*)B)[tid + i * 256] = ((const float4*)(Ws + 8192))[tid + i * 256]; // W3
    }
    __syncthreads();
    #pragma unroll
    for (int i = 0; i < 16; i++) {             // T = W2@W3
        int idx = tid * 16 + i, r = idx >> 6, c = idx & 63;
        float s = 0.f;
        #pragma unroll
        for (int k = 0; k < 64; k++) s += A[r * 64 + k] * B[k * 64 + c];
        T[idx] = s;
    }
    __syncthreads();
    #pragma unroll
    for (int i = 0; i < 4; i++)
        ((float4*)A)[tid + i * 256] = ((const float4*)Ws)[tid + i * 256];          // W1
    __syncthreads();
    #pragma unroll
    for (int i = 0; i < 16; i++) {             // W123 = W1@T
        int idx = tid * 16 + i, r = idx >> 6, c = idx & 63;
        float s = 0.f;
        #pragma unroll
        for (int k = 0; k < 64; k++) s += A[r * 64 + k] * T[k * 64 + c];
        g_W123[idx] = s;
    }
    if (tid < 64) {                            // bv2 = b1@T
        float s = 0.f;
        #pragma unroll
        for (int k = 0; k < 64; k++) s += bs[k] * T[k * 64 + tid];
        g_bv2[tid] = s;
    } else if (tid < 128) {                    // bv1 = b2@W3
        int c = tid - 64;
        float s = 0.f;
        #pragma unroll
        for (int k = 0; k < 64; k++) s += bs[64 + k] * B[k * 64 + c];
        g_bv1[c] = s;
    }
}

// ---------------------------------------------------------------------------
// Final GEMM (f32x2): out[remap(n)] = y3[n]@W123 + u2[n]*bv2 + u1[n]*bv1 + b3
// ---------------------------------------------------------------------------
__global__ void k_gemm_final(const float* __restrict__ x, const float* __restrict__ b3,
                             float* __restrict__ out) {
    __shared__ float Ws[64 * 64];
    __shared__ float Xs[32 * 68];
    int tid  = threadIdx.x;
    int row0 = blockIdx.x * 32;

    #pragma unroll
    for (int i = 0; i < 4; i++)
        ((float4*)Ws)[tid + i * 256] = ((const float4*)g_W123)[tid + i * 256];

    #pragma unroll
    for (int i = 0; i < 2; i++) {
        int idx = tid + i * 256;
        int r = idx >> 4, cc = idx & 15;
        int gr = row0 + r;
        float4 v = make_float4(0.f, 0.f, 0.f, 0.f);
        if (gr < NN) v = ((const float4*)x)[(size_t)gr * 16 + cc];
        *((float4*)&Xs[r * 68 + cc * 4]) = v;
    }
    __syncthreads();

    int r  = tid >> 3;
    int cb = (tid & 7) << 3;
    int gr = row0 + r;

    ull acc[4];
    {
        float un1 = (gr < NN) ? g_u1[gr] : 0.f;
        float un2 = (gr < NN) ? g_u2[gr] : 0.f;
        #pragma unroll
        for (int i = 0; i < 4; i++) {
            float lo = b3[cb + 2 * i]     + un2 * g_bv2[cb + 2 * i]     + un1 * g_bv1[cb + 2 * i];
            float hi = b3[cb + 2 * i + 1] + un2 * g_bv2[cb + 2 * i + 1] + un1 * g_bv1[cb + 2 * i + 1];
            asm("mov.b64 %0, {%1, %2};" : "=l"(acc[i]) : "f"(lo), "f"(hi));
        }
    }
    #pragma unroll
    for (int k = 0; k < 64; k++) {
        float xv = Xs[r * 68 + k];
        ull xvv;
        asm("mov.b64 %0, {%1, %1};" : "=l"(xvv) : "f"(xv));
        const ulonglong2* wp = (const ulonglong2*)&Ws[k * 64 + cb];
        ulonglong2 wa = wp[0], wb = wp[1];
        FMA2(acc[0], xvv, wa.x);
        FMA2(acc[1], xvv, wa.y);
        FMA2(acc[2], xvv, wb.x);
        FMA2(acc[3], xvv, wb.y);
    }
    if (gr < NN) {
        int orow = (gr < NU) ? gr : gr + NU;
        ulonglong2* o = (ulonglong2*)&out[(size_t)orow * 64 + cb];
        o[0] = make_ulonglong2(acc[0], acc[1]);
        o[1] = make_ulonglong2(acc[2], acc[3]);
    }
}

// ---------------------------------------------------------------------------
extern "C" void kernel_launch(void* const* d_in, const int* in_sizes, int n_in,
                              void* d_out, int out_size) {
    const int*   ei = (const int*)d_in[0];
    const float* ue = (const float*)d_in[1];
    const float* ie = (const float*)d_in[2];
    const float* Ws = (const float*)d_in[3];
    const float* bs = (const float*)d_in[4];
    float* out = (float*)d_out;

    float *bufA, *bufB, *bufC, *u1, *u2;
    int* cntp;
    cudaGetSymbolAddress((void**)&bufA, g_bufA);
    cudaGetSymbolAddress((void**)&bufB, g_bufB);
    cudaGetSymbolAddress((void**)&bufC, g_bufC);
    cudaGetSymbolAddress((void**)&u1,   g_u1);
    cudaGetSymbolAddress((void**)&u2,   g_u2);
    cudaGetSymbolAddress((void**)&cntp, g_cnt);

    const int TB = 256;
    cudaMemsetAsync(cntp, 0, NN * sizeof(int));
    k_prep   <<<(NN * 16 + TB - 1) / TB, TB>>>(ue, ie, out);          // 1
    k_deg    <<<(NE + TB - 1) / TB, TB>>>(ei);                        // 2
    k_scan1  <<<NBLK, SCAN_B>>>();                                    // 3
    k_scanfin<<<NBLK, SCAN_B>>>();                                    // 4
    k_fill   <<<(NE + TB - 1) / TB, TB>>>(ei);                        // 5
    k_agg<false, true ><<<(NN * 8 + TB - 1) / TB, TB>>>(bufC, nullptr, u1, bufA); // 6 <- ncu -s 5
    k_agg<true,  true ><<<(NN * 8 + TB - 1) / TB, TB>>>(bufA, u1, u2, bufB);      // 7
    k_agg<false, false><<<(NN * 8 + TB - 1) / TB, TB>>>(bufB, nullptr, nullptr, bufA); // 8
    k_wprod  <<<1, 256>>>(Ws, bs);                                    // 9
    k_gemm_final<<<(NN + 31) / 32, TB>>>(bufA, bs + 2 * 64, out);     // 10
}

// round 5
// speedup vs baseline: 2.0510x; 1.0421x over previous
#include <cuda_runtime.h>

#define NU 100000
#define NI 50000
#define NN 150000
#define HD 64
#define NE 1200000
#define SCAN_B 1024
#define NBLK ((NN + SCAN_B - 1) / SCAN_B)   // 147

typedef unsigned long long ull;

// Scratch (static device globals)
__device__ float g_bufA[NN * HD];
__device__ float g_bufB[NN * HD];
__device__ float g_u1[NN];
__device__ float g_u2[NN];
__device__ int   g_cnt[NN];          // edge in-degree (self loop NOT included)
__device__ int   g_flag[NBLK];       // scan: part+1 (0 = not ready)
__device__ int   g_off[NN + 1];
__device__ int   g_cur[NN];
__device__ int2  g_edge[NE];         // {src, norm bits}, bucketed by dst
__device__ float g_W123[HD * HD];    // W1@W2@W3
__device__ float g_bv1[HD];          // b2@W3
__device__ float g_bv2[HD];          // b1@W2@W3

#define FMA2(acc, a, b) \
    asm("fma.rn.f32x2 %0, %1, %2, %0;" : "+l"(acc) : "l"(a), "l"(b))
#define MUL2(d, a, b) \
    asm("mul.rn.f32x2 %0, %1, %2;" : "=l"(d) : "l"(a), "l"(b))

// ---------------------------------------------------------------------------
// Degree count (also re-zeroes scan flags for this replay)
// ---------------------------------------------------------------------------
__global__ void k_deg(const int* __restrict__ ei) {
    int e = blockIdx.x * blockDim.x + threadIdx.x;
    if (e < NBLK) g_flag[e] = 0;
    if (e < NE) atomicAdd(&g_cnt[ei[NE + e]], 1);
}

// ---------------------------------------------------------------------------
// Single-pass scan of g_cnt -> g_off (exclusive+1), g_cur.
// All 147 blocks co-resident (1 wave); each publishes its block total as
// part+1 in g_flag, then sums all predecessor totals (order-independent).
// ---------------------------------------------------------------------------
__global__ void k_scan() {
    __shared__ int ws[32];
    __shared__ int base;
    int tid = threadIdx.x;
    if (tid == 0) base = 0;
    int i = blockIdx.x * SCAN_B + tid;
    int lane = tid & 31, wid = tid >> 5;
    int cnt = (i < NN) ? g_cnt[i] : 0;
    int x = cnt;
    #pragma unroll
    for (int o = 1; o < 32; o <<= 1) {
        int y = __shfl_up_sync(0xffffffffu, x, o);
        if (lane >= o) x += y;
    }
    if (lane == 31) ws[wid] = x;
    __syncthreads();
    if (wid == 0) {
        int s = ws[lane];
        #pragma unroll
        for (int o = 1; o < 32; o <<= 1) {
            int y = __shfl_up_sync(0xffffffffu, s, o);
            if (lane >= o) s += y;
        }
        ws[lane] = s;
    }
    __syncthreads();
    int incl = x + (wid > 0 ? ws[wid - 1] : 0);

    // publish this block's total (single word, value = total + 1)
    if (tid == SCAN_B - 1)
        *((volatile int*)&g_flag[blockIdx.x]) = incl + 1;

    // sum all predecessor block totals
    if (tid < blockIdx.x) {
        int v;
        do { v = *((volatile int*)&g_flag[tid]); } while (v == 0);
        atomicAdd(&base, v - 1);
    }
    __syncthreads();

    if (i < NN) {
        int g = incl + base;
        g_off[i + 1] = g;
        g_cur[i] = g - cnt;
        if (i == 0) g_off[0] = 0;
    }
}

// ---------------------------------------------------------------------------
__global__ void k_fill(const int* __restrict__ ei) {
    int e = blockIdx.x * blockDim.x + threadIdx.x;
    if (e >= NE) return;
    int s = ei[e];
    int d = ei[NE + e];
    float nrm = rsqrtf((float)(g_cnt[s] + 1)) * rsqrtf((float)(g_cnt[d] + 1));
    int pos = atomicAdd(&g_cur[d], 1);
    g_edge[pos] = make_int2(s, __float_as_int(nrm));
}

// ---------------------------------------------------------------------------
// Aggregation: y[i] = inv_i * x[i] + sum_e nrm_e * x[src_e]
// 8 threads/node, each owns 8 cols. Width-8 shuffle broadcast + edge prefetch.
// ---------------------------------------------------------------------------
template<bool SPLIT, bool UIN, bool UOUT>
__global__ void k_agg(const float* __restrict__ xA, const float* __restrict__ xB,
                      const float* __restrict__ u_in, float* __restrict__ u_out,
                      float* __restrict__ y) {
    int t = blockIdx.x * blockDim.x + threadIdx.x;
    int node = t >> 3;
    int c = t & 7;
    if (node >= NN) return;
    unsigned gmask = 0xFFu << (threadIdx.x & 24);

    int beg = g_off[node];
    int end = g_off[node + 1];
    float inv = 1.0f / (float)(end - beg + 1);
    ull pinv;
    asm("mov.b64 %0, {%1, %1};" : "=l"(pinv) : "f"(inv));

    const float* selfp = SPLIT ? (node < NU ? xA + (size_t)node * 64
                                            : xB + (size_t)(node - NU) * 64)
                               : xA + (size_t)node * 64;
    ulonglong2 s0 = *(const ulonglong2*)(selfp + c * 8);
    ulonglong2 s1 = *(const ulonglong2*)(selfp + c * 8 + 4);
    ull acc0, acc1, acc2, acc3;
    MUL2(acc0, s0.x, pinv); MUL2(acc1, s0.y, pinv);
    MUL2(acc2, s1.x, pinv); MUL2(acc3, s1.y, pinv);

    float uacc = UOUT ? inv * (UIN ? u_in[node] : 1.0f) : 0.0f;

    int idx = beg + c;
    int2 ed = (idx < end) ? g_edge[idx] : make_int2(0, 0);
    for (int j0 = beg; j0 < end; j0 += 8) {
        int nidx = j0 + 8 + c;
        int2 edn = (nidx < end) ? g_edge[nidx] : make_int2(0, 0);
        int m = min(8, end - j0);
        #pragma unroll 4
        for (int k = 0; k < m; k++) {
            int      s  = __shfl_sync(gmask, ed.x, k, 8);
            unsigned wb = (unsigned)__shfl_sync(gmask, ed.y, k, 8);
            ull ww;
            asm("mov.b64 %0, {%1, %1};" : "=l"(ww) : "r"(wb));
            const float* hp = SPLIT ? (s < NU ? xA + (size_t)s * 64
                                              : xB + (size_t)(s - NU) * 64)
                                    : xA + (size_t)s * 64;
            ulonglong2 h0 = *(const ulonglong2*)(hp + c * 8);
            ulonglong2 h1 = *(const ulonglong2*)(hp + c * 8 + 4);
            FMA2(acc0, ww, h0.x); FMA2(acc1, ww, h0.y);
            FMA2(acc2, ww, h1.x); FMA2(acc3, ww, h1.y);
            if (UOUT && c == 0)
                uacc += __uint_as_float(wb) * (UIN ? u_in[s] : 1.0f);
        }
        ed = edn;
    }

    ulonglong2* yo = (ulonglong2*)(y + (size_t)node * 64 + c * 8);
    yo[0] = make_ulonglong2(acc0, acc1);
    yo[1] = make_ulonglong2(acc2, acc3);
    if (UOUT && c == 0) u_out[node] = uacc;
}

// ---------------------------------------------------------------------------
// W123 = W1@W2@W3, bv2 = b1@W2@W3, bv1 = b2@W3. One block, 256 threads.
// ---------------------------------------------------------------------------
__global__ void k_wprod(const float* __restrict__ Ws, const float* __restrict__ bs) {
    __shared__ float A[4096], B[4096], T[4096];
    int tid = threadIdx.x;
    #pragma unroll
    for (int i = 0; i < 4; i++) {
        ((float4*)A)[tid + i * 256] = ((const float4*)(Ws + 4096))[tid + i * 256]; // W2
        ((float4*)B)[tid + i * 256] = ((const float4*)(Ws + 8192))[tid + i * 256]; // W3
    }
    __syncthreads();
    #pragma unroll
    for (int i = 0; i < 16; i++) {             // T = W2@W3
        int idx = tid * 16 + i, r = idx >> 6, c = idx & 63;
        float s = 0.f;
        #pragma unroll
        for (int k = 0; k < 64; k++) s += A[r * 64 + k] * B[k * 64 + c];
        T[idx] = s;
    }
    __syncthreads();
    #pragma unroll
    for (int i = 0; i < 4; i++)
        ((float4*)A)[tid + i * 256] = ((const float4*)Ws)[tid + i * 256];          // W1
    __syncthreads();
    #pragma unroll
    for (int i = 0; i < 16; i++) {             // W123 = W1@T
        int idx = tid * 16 + i, r = idx >> 6, c = idx & 63;
        float s = 0.f;
        #pragma unroll
        for (int k = 0; k < 64; k++) s += A[r * 64 + k] * T[k * 64 + c];
        g_W123[idx] = s;
    }
    if (tid < 64) {                            // bv2 = b1@T
        float s = 0.f;
        #pragma unroll
        for (int k = 0; k < 64; k++) s += bs[k] * T[k * 64 + tid];
        g_bv2[tid] = s;
    } else if (tid < 128) {                    // bv1 = b2@W3
        int c = tid - 64;
        float s = 0.f;
        #pragma unroll
        for (int k = 0; k < 64; k++) s += bs[64 + k] * B[k * 64 + c];
        g_bv1[c] = s;
    }
}

// ---------------------------------------------------------------------------
// Fused agg3 + final GEMM:
//   y3 = A~ @ x (staged in smem), out[remap] = y3@W123 + u2*bv2 + u1*bv1 + b3
// 256 threads = 32 nodes x 8 threads; gemm reuses the same row/col mapping.
// ---------------------------------------------------------------------------
__global__ void k_agg_gemm(const float* __restrict__ x, const float* __restrict__ b3,
                           float* __restrict__ out) {
    __shared__ float Ws[64 * 64];
    __shared__ float Xs[32 * 68];
    int tid = threadIdx.x;

    #pragma unroll
    for (int i = 0; i < 4; i++)
        ((float4*)Ws)[tid + i * 256] = ((const float4*)g_W123)[tid + i * 256];

    int row0 = blockIdx.x * 32;
    int r = tid >> 3;
    int c = tid & 7;
    int node = row0 + r;
    unsigned gmask = 0xFFu << (threadIdx.x & 24);

    if (node < NN) {
        int beg = g_off[node];
        int end = g_off[node + 1];
        float inv = 1.0f / (float)(end - beg + 1);
        ull pinv;
        asm("mov.b64 %0, {%1, %1};" : "=l"(pinv) : "f"(inv));

        const float* xc = x + c * 8;
        ulonglong2 s0 = *(const ulonglong2*)(xc + (size_t)node * 64);
        ulonglong2 s1 = *(const ulonglong2*)(xc + (size_t)node * 64 + 4);
        ull acc0, acc1, acc2, acc3;
        MUL2(acc0, s0.x, pinv); MUL2(acc1, s0.y, pinv);
        MUL2(acc2, s1.x, pinv); MUL2(acc3, s1.y, pinv);

        int idx = beg + c;
        int2 ed = (idx < end) ? g_edge[idx] : make_int2(0, 0);
        for (int j0 = beg; j0 < end; j0 += 8) {
            int nidx = j0 + 8 + c;
            int2 edn = (nidx < end) ? g_edge[nidx] : make_int2(0, 0);
            int m = min(8, end - j0);
            #pragma unroll 4
            for (int k = 0; k < m; k++) {
                int      s  = __shfl_sync(gmask, ed.x, k, 8);
                unsigned wb = (unsigned)__shfl_sync(gmask, ed.y, k, 8);
                ull ww;
                asm("mov.b64 %0, {%1, %1};" : "=l"(ww) : "r"(wb));
                ulonglong2 h0 = *(const ulonglong2*)(xc + (size_t)s * 64);
                ulonglong2 h1 = *(const ulonglong2*)(xc + (size_t)s * 64 + 4);
                FMA2(acc0, ww, h0.x); FMA2(acc1, ww, h0.y);
                FMA2(acc2, ww, h1.x); FMA2(acc3, ww, h1.y);
            }
            ed = edn;
        }
        ulonglong2* xr = (ulonglong2*)&Xs[r * 68 + c * 8];
        xr[0] = make_ulonglong2(acc0, acc1);
        xr[1] = make_ulonglong2(acc2, acc3);
    }
    __syncthreads();

    // GEMM phase: same thread -> (row r, cols c*8..c*8+7)
    int cb = c << 3;
    int gr = node;
    ull acc[4];
    {
        float un1 = (gr < NN) ? g_u1[gr] : 0.f;
        float un2 = (gr < NN) ? g_u2[gr] : 0.f;
        #pragma unroll
        for (int i = 0; i < 4; i++) {
            float lo = b3[cb + 2 * i]     + un2 * g_bv2[cb + 2 * i]     + un1 * g_bv1[cb + 2 * i];
            float hi = b3[cb + 2 * i + 1] + un2 * g_bv2[cb + 2 * i + 1] + un1 * g_bv1[cb + 2 * i + 1];
            asm("mov.b64 %0, {%1, %2};" : "=l"(acc[i]) : "f"(lo), "f"(hi));
        }
    }
    #pragma unroll
    for (int k = 0; k < 64; k++) {
        float xv = Xs[r * 68 + k];
        ull xvv;
        asm("mov.b64 %0, {%1, %1};" : "=l"(xvv) : "f"(xv));
        const ulonglong2* wp = (const ulonglong2*)&Ws[k * 64 + cb];
        ulonglong2 wa = wp[0], wb2 = wp[1];
        FMA2(acc[0], xvv, wa.x);
        FMA2(acc[1], xvv, wa.y);
        FMA2(acc[2], xvv, wb2.x);
        FMA2(acc[3], xvv, wb2.y);
    }
    if (gr < NN) {
        int orow = (gr < NU) ? gr : gr + NU;
        ulonglong2* o = (ulonglong2*)&out[(size_t)orow * 64 + cb];
        o[0] = make_ulonglong2(acc[0], acc[1]);
        o[1] = make_ulonglong2(acc[2], acc[3]);
    }
}

// ---------------------------------------------------------------------------
// Copy raw embeddings into output segments 1 (users) and 3 (items)
// ---------------------------------------------------------------------------
__global__ void k_embcopy(const float* __restrict__ ue, const float* __restrict__ ie,
                          float* __restrict__ out) {
    int t = blockIdx.x * blockDim.x + threadIdx.x;
    if (t < NU * 16) {
        ((float4*)out)[NU * 16 + t] = ((const float4*)ue)[t];
    } else if (t < NN * 16) {
        int q = t - NU * 16;
        ((float4*)out)[(2 * NU + NI) * 16 + q] = ((const float4*)ie)[q];
    }
}

// ---------------------------------------------------------------------------
extern "C" void kernel_launch(void* const* d_in, const int* in_sizes, int n_in,
                              void* d_out, int out_size) {
    const int*   ei = (const int*)d_in[0];
    const float* ue = (const float*)d_in[1];
    const float* ie = (const float*)d_in[2];
    const float* Ws = (const float*)d_in[3];
    const float* bs = (const float*)d_in[4];
    float* out = (float*)d_out;

    float *bufA, *bufB, *u1, *u2;
    int* cntp;
    cudaGetSymbolAddress((void**)&bufA, g_bufA);
    cudaGetSymbolAddress((void**)&bufB, g_bufB);
    cudaGetSymbolAddress((void**)&u1,   g_u1);
    cudaGetSymbolAddress((void**)&u2,   g_u2);
    cudaGetSymbolAddress((void**)&cntp, g_cnt);

    const int TB = 256;
    cudaMemsetAsync(cntp, 0, NN * sizeof(int));
    k_deg <<<(NE + TB - 1) / TB, TB>>>(ei);                                        // 1
    k_scan<<<NBLK, SCAN_B>>>();                                                    // 2
    k_fill<<<(NE + TB - 1) / TB, TB>>>(ei);                                        // 3
    k_agg<true,  false, true ><<<(NN * 8 + TB - 1) / TB, TB>>>(ue, ie, nullptr, u1, bufA);   // 4 <- profiled
    k_agg<false, true,  true ><<<(NN * 8 + TB - 1) / TB, TB>>>(bufA, bufA, u1, u2, bufB);    // 5
    k_wprod<<<1, 256>>>(Ws, bs);                                                   // 6
    k_agg_gemm<<<(NN + 31) / 32, TB>>>(bufB, bs + 2 * 64, out);                    // 7
    k_embcopy<<<(NN * 16 + TB - 1) / TB, TB>>>(ue, ie, out);                       // 8
}